// round 1
// baseline (speedup 1.0000x reference)
#include <cuda_runtime.h>

// FEDformer FourierBlock + out-projection + residual + series decomposition,
// fully fused. Key simplifications (mathematically exact vs reference):
//  - k/v projections unused by FourierBlock -> skipped
//  - bq contributes only to DFT mode 0; kept modes are {1,4,5} -> dropped
//  - rfft/irfft with 3 kept modes -> direct 3-mode DFT / inverse
//  - Wq and Wo commute with the time-axis DFT -> applied to 3 mode vectors,
//    not to all 96 timesteps
//  - moving_avg(k=25, edge pad) via per-column prefix sums in smem

#define NNODES 2000
#define LSEQ   96
#define DM     32
#define HH     4
#define EE     8
#define MM     3
#define KAVG   25
#define PAD    12        // (KAVG-1)/2
#define TPB    128

__global__ __launch_bounds__(TPB) void feldm_kernel(
    const float* __restrict__ x,
    const float* __restrict__ Wq,
    const float* __restrict__ Wo,
    const float* __restrict__ bo,
    const float* __restrict__ W1,
    const float* __restrict__ W2,
    float* __restrict__ out)
{
    const int tid = threadIdx.x;
    const int b = blockIdx.x & 7;        // n-major: 8 consecutive blocks share node n
    const int n = blockIdx.x >> 3;
    const size_t base = ((size_t)b * NNODES + n) * (size_t)(LSEQ * DM);

    __shared__ float sx[LSEQ * DM];          // x tile, later xr = x + new_x
    __shared__ float sS[(LSEQ + 1) * DM];    // column prefix sums
    __shared__ float sw1[HH*EE*EE*MM];       // 768
    __shared__ float sw2[HH*EE*EE*MM];
    __shared__ float ctab[MM * LSEQ];
    __shared__ float stab[MM * LSEQ];
    __shared__ float Xfr[96], Xfi[96];       // DFT of x  (3 modes x 32 dims)
    __shared__ float Xr[96],  Xi[96];        // after Wq
    __shared__ float Yr[96],  Yi[96];        // after per-node complex weights
    __shared__ float Pr[96],  Pi[96];        // after Wo, scaled 2/L

    // ---- load x tile (vectorized) ----
    {
        const float4* xg = (const float4*)(x + base);
        float4* sdst = (float4*)sx;
        #pragma unroll
        for (int i = tid; i < (LSEQ * DM) / 4; i += TPB) sdst[i] = xg[i];
    }
    // ---- load per-node complex weights ----
    {
        const float* w1g = W1 + (size_t)n * (HH*EE*EE*MM);
        const float* w2g = W2 + (size_t)n * (HH*EE*EE*MM);
        for (int i = tid; i < HH*EE*EE*MM; i += TPB) { sw1[i] = w1g[i]; sw2[i] = w2g[i]; }
    }
    // ---- twiddle tables: cos/sin(2*pi*mode*t/L) ----
    for (int i = tid; i < MM * LSEQ; i += TPB) {
        int m = i / LSEQ, t = i - m * LSEQ;
        const int mode = (m == 0) ? 1 : (m == 1 ? 4 : 5);
        float sv, cv;
        sincospif(2.0f * (float)(mode * t) / (float)LSEQ, &sv, &cv);
        ctab[i] = cv; stab[i] = sv;
    }
    __syncthreads();

    // ---- forward DFT at 3 modes: Xf[m][d] = sum_t x[t][d] e^{-i w_m t} ----
    if (tid < 96) {
        const int m = tid >> 5, d = tid & 31;
        const float* ct = ctab + m * LSEQ;
        const float* st = stab + m * LSEQ;
        float ar = 0.f, ai = 0.f;
        #pragma unroll 8
        for (int t = 0; t < LSEQ; ++t) {
            const float v = sx[t * DM + d];
            ar = fmaf(v, ct[t], ar);
            ai = fmaf(-v, st[t], ai);
        }
        Xfr[tid] = ar; Xfi[tid] = ai;
    }
    __syncthreads();

    // ---- X = Xf @ Wq^T   (q = x @ Wq^T; DFT commutes with Wq) ----
    if (tid < 96) {
        const int m = tid >> 5, j = tid & 31;
        const float* wr = Wq + j * DM;
        float ar = 0.f, ai = 0.f;
        #pragma unroll
        for (int d = 0; d < DM; ++d) {
            const float w = __ldg(wr + d);
            ar = fmaf(Xfr[(m << 5) + d], w, ar);
            ai = fmaf(Xfi[(m << 5) + d], w, ai);
        }
        Xr[tid] = ar; Xi[tid] = ai;
    }
    __syncthreads();

    // ---- Y[m][h][o] = sum_e X[m][h*8+e] * (W1 + iW2)[n][h][e][o][m] ----
    if (tid < 96) {
        const int m = tid >> 5, ho = tid & 31, h = ho >> 3, o = ho & 7;
        float yr = 0.f, yi = 0.f;
        #pragma unroll
        for (int e = 0; e < EE; ++e) {
            const int wi = ((h * EE + e) * EE + o) * MM + m;
            const float w1v = sw1[wi], w2v = sw2[wi];
            const float xr = Xr[(m << 5) + (h << 3) + e];
            const float xi = Xi[(m << 5) + (h << 3) + e];
            yr = fmaf(xr, w1v, fmaf(-xi, w2v, yr));
            yi = fmaf(xr, w2v, fmaf( xi, w1v, yi));
        }
        Yr[tid] = yr; Yi[tid] = yi;
    }
    __syncthreads();

    // ---- P[m][d] = (2/L) * sum_j Y[m][j] * Wo[d][j] ----
    if (tid < 96) {
        const int m = tid >> 5, d = tid & 31;
        const float* wr = Wo + d * DM;
        float pr = 0.f, pi = 0.f;
        #pragma unroll
        for (int j = 0; j < DM; ++j) {
            const float w = __ldg(wr + j);
            pr = fmaf(Yr[(m << 5) + j], w, pr);
            pi = fmaf(Yi[(m << 5) + j], w, pi);
        }
        Pr[tid] = pr * (2.0f / (float)LSEQ);
        Pi[tid] = pi * (2.0f / (float)LSEQ);
    }
    __syncthreads();

    // ---- xr = x + new_x  (inverse 3-mode transform + bo) ----
    for (int i = tid; i < LSEQ * DM; i += TPB) {
        const int t = i >> 5, d = i & 31;
        float acc = __ldg(bo + d);
        #pragma unroll
        for (int m = 0; m < MM; ++m)
            acc += Pr[(m << 5) + d] * ctab[m * LSEQ + t]
                 - Pi[(m << 5) + d] * stab[m * LSEQ + t];
        sx[i] += acc;
    }
    __syncthreads();

    // ---- per-column prefix sums (one warp, 32 columns) ----
    if (tid < 32) {
        const int d = tid;
        float run = 0.f;
        sS[d] = 0.f;
        #pragma unroll 8
        for (int t = 0; t < LSEQ; ++t) {
            run += sx[t * DM + d];
            sS[(t + 1) * DM + d] = run;
        }
    }
    __syncthreads();

    // ---- trend (moving avg, edge-replicated) and residual; store ----
    {
        float* og = out + base;
        for (int i = tid; i < LSEQ * DM; i += TPB) {
            const int t = i >> 5, d = i & 31;
            const int lo = t - PAD, hi = t + PAD;
            const int lcl = lo < 0 ? 0 : lo;
            const int hcl = hi > (LSEQ - 1) ? (LSEQ - 1) : hi;
            float sum = sS[(hcl + 1) * DM + d] - sS[lcl * DM + d];
            if (lo < 0)          sum += (float)(-lo) * sx[d];                  // replicate x[0]
            if (hi > LSEQ - 1)   sum += (float)(hi - (LSEQ - 1)) * sx[(LSEQ - 1) * DM + d];
            const float trend = sum * (1.0f / (float)KAVG);
            og[i] = sx[i] - trend;
        }
    }
}

extern "C" void kernel_launch(void* const* d_in, const int* in_sizes, int n_in,
                              void* d_out, int out_size) {
    // metadata order: x, Wq, bq, Wk, bk, Wv, bv, Wo, bo, W1, W2
    const float* x  = (const float*)d_in[0];
    const float* Wq = (const float*)d_in[1];
    // d_in[2] = bq (only affects mode 0 -> unused), d_in[3..6] = Wk/bk/Wv/bv (unused)
    const float* Wo = (const float*)d_in[7];
    const float* bo = (const float*)d_in[8];
    const float* W1 = (const float*)d_in[9];
    const float* W2 = (const float*)d_in[10];
    float* out = (float*)d_out;

    const int B = 8;
    dim3 grid(NNODES * B);   // n-major: blocks n*8+b share node-n weights in L2
    feldm_kernel<<<grid, TPB>>>(x, Wq, Wo, bo, W1, W2, out);
}

// round 2
// speedup vs baseline: 2.7376x; 2.7376x over previous
#include <cuda_runtime.h>

// FEDformer FourierBlock + out-projection + residual + series decomposition.
// R2: register-twiddle 3-mode DFT on all threads, smem-staged Wq/Wo with
// rotated conflict-free indexing, sliding-window moving average (no prefix
// array), warp-local mid phases.

#define NNODES 2000
#define LSEQ   96
#define DM     32
#define HH     4
#define EE     8
#define MM     3
#define KAVG   25
#define PAD    12
#define TPB    128

__global__ __launch_bounds__(TPB) void feldm_kernel(
    const float* __restrict__ x,
    const float* __restrict__ Wq,
    const float* __restrict__ Wo,
    const float* __restrict__ bo,
    const float* __restrict__ W1,
    const float* __restrict__ W2,
    float* __restrict__ out)
{
    const int tid  = threadIdx.x;
    const int w    = tid >> 5;
    const int lane = tid & 31;
    const int b = blockIdx.x & 7;        // n-major: 8 consecutive blocks share node n
    const int n = blockIdx.x >> 3;
    const size_t base = ((size_t)b * NNODES + n) * (size_t)(LSEQ * DM);

    __shared__ float sx[LSEQ * DM];                 // 12 KB: x, then xr in place
    __shared__ float sw1[HH*EE*EE*MM];              // 3 KB
    __shared__ float sw2[HH*EE*EE*MM];              // 3 KB
    __shared__ float sWq[DM*DM];                    // 4 KB
    __shared__ float sWo[DM*DM];                    // 4 KB
    __shared__ float spart[4*6*32];                 // 3 KB DFT partials [w][m][ri][d]
    __shared__ float Xfr[96], Xfi[96];
    __shared__ float Xr[96],  Xi[96];
    __shared__ float Yr[96],  Yi[96];
    __shared__ float Pr[96],  Pi[96];

    // ---- stage x (float4), Wq/Wo (float4), per-node W1/W2 ----
    {
        const float4* xg = (const float4*)(x + base);
        float4* s4 = (float4*)sx;
        #pragma unroll
        for (int i = tid; i < (LSEQ*DM)/4; i += TPB) s4[i] = xg[i];
        const float4* qg = (const float4*)Wq;
        const float4* og = (const float4*)Wo;
        float4* q4 = (float4*)sWq;
        float4* o4 = (float4*)sWo;
        #pragma unroll
        for (int i = tid; i < (DM*DM)/4; i += TPB) { q4[i] = qg[i]; o4[i] = og[i]; }
        const float* w1g = W1 + (size_t)n * (HH*EE*EE*MM);
        const float* w2g = W2 + (size_t)n * (HH*EE*EE*MM);
        #pragma unroll
        for (int i = tid; i < HH*EE*EE*MM; i += TPB) { sw1[i] = w1g[i]; sw2[i] = w2g[i]; }
    }
    __syncthreads();

    // ---- rotation step constants: e^{i*2pi*mode*4/96}, modes {1,4,5} ----
    float pc1, ps1, pc2, ps2, pc3, ps3;
    sincospif(1.0f/12.0f, &ps1, &pc1);
    sincospif(4.0f/12.0f, &ps2, &pc2);
    sincospif(5.0f/12.0f, &ps3, &pc3);

    // ---- forward 3-mode DFT, t = w + 4i (i=0..23), d = lane ----
    {
        float c1,s1,c2,s2,c3,s3;
        sincospif(1.0f*w/48.0f, &s1, &c1);
        sincospif(4.0f*w/48.0f, &s2, &c2);
        sincospif(5.0f*w/48.0f, &s3, &c3);
        float ar1=0.f, ai1=0.f, ar2=0.f, ai2=0.f, ar3=0.f, ai3=0.f;
        #pragma unroll
        for (int i = 0; i < 24; ++i) {
            const float v = sx[((i<<2) + w)*DM + lane];
            ar1 = fmaf(v, c1, ar1);  ai1 = fmaf(v, s1, ai1);
            ar2 = fmaf(v, c2, ar2);  ai2 = fmaf(v, s2, ai2);
            ar3 = fmaf(v, c3, ar3);  ai3 = fmaf(v, s3, ai3);
            float nc, ns;
            nc = fmaf(c1, pc1, -s1*ps1); ns = fmaf(s1, pc1,  c1*ps1); c1 = nc; s1 = ns;
            nc = fmaf(c2, pc2, -s2*ps2); ns = fmaf(s2, pc2,  c2*ps2); c2 = nc; s2 = ns;
            nc = fmaf(c3, pc3, -s3*ps3); ns = fmaf(s3, pc3,  c3*ps3); c3 = nc; s3 = ns;
        }
        spart[(w*6 + 0)*32 + lane] = ar1;  spart[(w*6 + 1)*32 + lane] = ai1;
        spart[(w*6 + 2)*32 + lane] = ar2;  spart[(w*6 + 3)*32 + lane] = ai2;
        spart[(w*6 + 4)*32 + lane] = ar3;  spart[(w*6 + 5)*32 + lane] = ai3;
    }
    __syncthreads();

    // ---- mid phases: reduce -> Wq -> node weights -> Wo (warp-local in m) ----
    if (tid < 96) {
        const int m = w, j = lane;
        // reduce partials; Xf = sum x*(cos - i sin)
        float fr = 0.f, fi = 0.f;
        #pragma unroll
        for (int ww = 0; ww < 4; ++ww) {
            fr += spart[(ww*6 + m*2 + 0)*32 + j];
            fi += spart[(ww*6 + m*2 + 1)*32 + j];
        }
        Xfr[tid] = fr; Xfi[tid] = -fi;
        __syncwarp();
        // X = Xf @ Wq^T   (rotated index: conflict-free)
        float arr = 0.f, aii = 0.f;
        #pragma unroll
        for (int k = 0; k < 32; ++k) {
            const int dd = (j + k) & 31;
            const float wv = sWq[j*DM + dd];
            arr = fmaf(Xfr[(m<<5) + dd], wv, arr);
            aii = fmaf(Xfi[(m<<5) + dd], wv, aii);
        }
        Xr[tid] = arr; Xi[tid] = aii;
        __syncwarp();
        // Y[m][h][o] = sum_e X[m][h*8+e] * (W1 + i W2)[h][e][o][m]
        const int h = j >> 3, o = j & 7;
        float yr = 0.f, yi = 0.f;
        #pragma unroll
        for (int e = 0; e < EE; ++e) {
            const int wi = ((h*EE + e)*EE + o)*MM + m;
            const float w1v = sw1[wi], w2v = sw2[wi];
            const float xr = Xr[(m<<5) + (h<<3) + e];
            const float xi = Xi[(m<<5) + (h<<3) + e];
            yr = fmaf(xr, w1v, fmaf(-xi, w2v, yr));
            yi = fmaf(xr, w2v, fmaf( xi, w1v, yi));
        }
        Yr[tid] = yr; Yi[tid] = yi;
        __syncwarp();
        // P = (2/L) * Y @ Wo^T   (rotated index)
        float pr = 0.f, pi = 0.f;
        #pragma unroll
        for (int k = 0; k < 32; ++k) {
            const int jj = (j + k) & 31;
            const float wv = sWo[j*DM + jj];
            pr = fmaf(Yr[(m<<5) + jj], wv, pr);
            pi = fmaf(Yi[(m<<5) + jj], wv, pi);
        }
        Pr[tid] = pr * (2.0f/(float)LSEQ);
        Pi[tid] = pi * (2.0f/(float)LSEQ);
    }
    __syncthreads();

    // ---- inverse 3-mode transform + residual (in place in sx) ----
    {
        float PrR0 = Pr[0*32 + lane], PiR0 = Pi[0*32 + lane];
        float PrR1 = Pr[1*32 + lane], PiR1 = Pi[1*32 + lane];
        float PrR2 = Pr[2*32 + lane], PiR2 = Pi[2*32 + lane];
        const float bod = __ldg(bo + lane);
        float c1,s1,c2,s2,c3,s3;
        sincospif(1.0f*w/48.0f, &s1, &c1);
        sincospif(4.0f*w/48.0f, &s2, &c2);
        sincospif(5.0f*w/48.0f, &s3, &c3);
        #pragma unroll
        for (int i = 0; i < 24; ++i) {
            const int idx = ((i<<2) + w)*DM + lane;
            float acc = bod;
            acc = fmaf(PrR0, c1, acc); acc = fmaf(-PiR0, s1, acc);
            acc = fmaf(PrR1, c2, acc); acc = fmaf(-PiR1, s2, acc);
            acc = fmaf(PrR2, c3, acc); acc = fmaf(-PiR2, s3, acc);
            sx[idx] += acc;
            float nc, ns;
            nc = fmaf(c1, pc1, -s1*ps1); ns = fmaf(s1, pc1,  c1*ps1); c1 = nc; s1 = ns;
            nc = fmaf(c2, pc2, -s2*ps2); ns = fmaf(s2, pc2,  c2*ps2); c2 = nc; s2 = ns;
            nc = fmaf(c3, pc3, -s3*ps3); ns = fmaf(s3, pc3,  c3*ps3); c3 = nc; s3 = ns;
        }
    }
    __syncthreads();

    // ---- sliding-window moving average + residual; warp w owns t in [24w, 24w+24) ----
    {
        const int t0 = w * 24;
        float win = 0.f;
        #pragma unroll
        for (int j = -PAD; j <= PAD; ++j) {
            int tt = t0 + j;
            tt = tt < 0 ? 0 : (tt > LSEQ-1 ? LSEQ-1 : tt);
            win += sx[tt*DM + lane];
        }
        float* og = out + base;
        #pragma unroll
        for (int i = 0; i < 24; ++i) {
            const int t = t0 + i;
            og[t*DM + lane] = sx[t*DM + lane] - win * (1.0f/(float)KAVG);
            int thi = t + PAD + 1; thi = thi > LSEQ-1 ? LSEQ-1 : thi;
            int tlo = t - PAD;     tlo = tlo < 0 ? 0 : tlo;
            win += sx[thi*DM + lane] - sx[tlo*DM + lane];
        }
    }
}

extern "C" void kernel_launch(void* const* d_in, const int* in_sizes, int n_in,
                              void* d_out, int out_size) {
    // metadata order: x, Wq, bq, Wk, bk, Wv, bv, Wo, bo, W1, W2
    const float* x  = (const float*)d_in[0];
    const float* Wq = (const float*)d_in[1];
    const float* Wo = (const float*)d_in[7];
    const float* bo = (const float*)d_in[8];
    const float* W1 = (const float*)d_in[9];
    const float* W2 = (const float*)d_in[10];
    float* out = (float*)d_out;

    const int B = in_sizes[0] / (NNODES * LSEQ * DM);
    dim3 grid(NNODES * B);
    feldm_kernel<<<grid, TPB>>>(x, Wq, Wo, bo, W1, W2, out);
}

// round 3
// speedup vs baseline: 3.4487x; 1.2598x over previous
#include <cuda_runtime.h>

// FEDformer FourierBlock + out-projection + residual + series decomposition.
// R3: shared float2 twiddle table (broadcast LDS) instead of register
// rotation chains -> cut regs 250 -> ~90, occupancy-driven win.

#define NNODES 2000
#define LSEQ   96
#define DM     32
#define HH     4
#define EE     8
#define MM     3
#define KAVG   25
#define PAD    12
#define TPB    128

__global__ __launch_bounds__(TPB, 6) void feldm_kernel(
    const float* __restrict__ x,
    const float* __restrict__ Wq,
    const float* __restrict__ Wo,
    const float* __restrict__ bo,
    const float* __restrict__ W1,
    const float* __restrict__ W2,
    float* __restrict__ out)
{
    const int tid  = threadIdx.x;
    const int w    = tid >> 5;
    const int lane = tid & 31;
    const int b = blockIdx.x & 7;        // n-major: 8 consecutive blocks share node n
    const int n = blockIdx.x >> 3;
    const size_t base = ((size_t)b * NNODES + n) * (size_t)(LSEQ * DM);

    __shared__ float  sx[LSEQ * DM];                // 12 KB: x, then xr in place
    __shared__ float  sw1[HH*EE*EE*MM];             // 3 KB
    __shared__ float  sw2[HH*EE*EE*MM];             // 3 KB
    __shared__ float  sWq[DM*DM];                   // 4 KB
    __shared__ float  sWo[DM*DM];                   // 4 KB
    __shared__ float  spart[4*6*32];                // 3 KB DFT partials
    __shared__ float2 tw[MM * LSEQ];                // 2.25 KB (cos,sin) tables
    __shared__ float  Xfr[96], Xfi[96];
    __shared__ float  Xr[96],  Xi[96];
    __shared__ float  Yr[96],  Yi[96];
    __shared__ float  Pr[96],  Pi[96];

    // ---- stage x (float4), Wq/Wo (float4), per-node W1/W2, twiddles ----
    {
        const float4* xg = (const float4*)(x + base);
        float4* s4 = (float4*)sx;
        #pragma unroll
        for (int i = tid; i < (LSEQ*DM)/4; i += TPB) s4[i] = xg[i];
        const float4* qg = (const float4*)Wq;
        const float4* og = (const float4*)Wo;
        float4* q4 = (float4*)sWq;
        float4* o4 = (float4*)sWo;
        #pragma unroll
        for (int i = tid; i < (DM*DM)/4; i += TPB) { q4[i] = qg[i]; o4[i] = og[i]; }
        const float* w1g = W1 + (size_t)n * (HH*EE*EE*MM);
        const float* w2g = W2 + (size_t)n * (HH*EE*EE*MM);
        #pragma unroll
        for (int i = tid; i < HH*EE*EE*MM; i += TPB) { sw1[i] = w1g[i]; sw2[i] = w2g[i]; }
        // twiddle tables: (cos,sin)(2*pi*mode*t/96), modes {1,4,5}
        #pragma unroll
        for (int i = tid; i < MM*LSEQ; i += TPB) {
            const int m = i / LSEQ, t = i - m * LSEQ;
            const int mode = (m == 0) ? 1 : (m == 1 ? 4 : 5);
            float sv, cv;
            sincospif((float)(mode * t) / 48.0f, &sv, &cv);
            tw[i] = make_float2(cv, sv);
        }
    }
    __syncthreads();

    // ---- forward 3-mode DFT: t = w + 4i (i=0..23), d = lane ----
    {
        float ar1=0.f, ai1=0.f, ar2=0.f, ai2=0.f, ar3=0.f, ai3=0.f;
        #pragma unroll 6
        for (int i = 0; i < 24; ++i) {
            const int t = (i << 2) + w;
            const float v = sx[t*DM + lane];
            const float2 w1 = tw[t];
            const float2 w2 = tw[LSEQ + t];
            const float2 w3 = tw[2*LSEQ + t];
            ar1 = fmaf(v, w1.x, ar1);  ai1 = fmaf(v, w1.y, ai1);
            ar2 = fmaf(v, w2.x, ar2);  ai2 = fmaf(v, w2.y, ai2);
            ar3 = fmaf(v, w3.x, ar3);  ai3 = fmaf(v, w3.y, ai3);
        }
        spart[(w*6 + 0)*32 + lane] = ar1;  spart[(w*6 + 1)*32 + lane] = ai1;
        spart[(w*6 + 2)*32 + lane] = ar2;  spart[(w*6 + 3)*32 + lane] = ai2;
        spart[(w*6 + 4)*32 + lane] = ar3;  spart[(w*6 + 5)*32 + lane] = ai3;
    }
    __syncthreads();

    // ---- mid phases: reduce -> Wq -> node weights -> Wo (warp-local in m) ----
    if (tid < 96) {
        const int m = w, j = lane;
        // reduce partials; Xf = sum x*(cos - i sin)
        float fr = 0.f, fi = 0.f;
        #pragma unroll
        for (int ww = 0; ww < 4; ++ww) {
            fr += spart[(ww*6 + m*2 + 0)*32 + j];
            fi += spart[(ww*6 + m*2 + 1)*32 + j];
        }
        Xfr[tid] = fr; Xfi[tid] = -fi;
        __syncwarp();
        // X = Xf @ Wq^T   (rotated index: conflict-free)
        float arr = 0.f, aii = 0.f;
        #pragma unroll 8
        for (int k = 0; k < 32; ++k) {
            const int dd = (j + k) & 31;
            const float wv = sWq[j*DM + dd];
            arr = fmaf(Xfr[(m<<5) + dd], wv, arr);
            aii = fmaf(Xfi[(m<<5) + dd], wv, aii);
        }
        Xr[tid] = arr; Xi[tid] = aii;
        __syncwarp();
        // Y[m][h][o] = sum_e X[m][h*8+e] * (W1 + i W2)[h][e][o][m]
        const int h = j >> 3, o = j & 7;
        float yr = 0.f, yi = 0.f;
        #pragma unroll
        for (int e = 0; e < EE; ++e) {
            const int wi = ((h*EE + e)*EE + o)*MM + m;
            const float w1v = sw1[wi], w2v = sw2[wi];
            const float xr = Xr[(m<<5) + (h<<3) + e];
            const float xi = Xi[(m<<5) + (h<<3) + e];
            yr = fmaf(xr, w1v, fmaf(-xi, w2v, yr));
            yi = fmaf(xr, w2v, fmaf( xi, w1v, yi));
        }
        Yr[tid] = yr; Yi[tid] = yi;
        __syncwarp();
        // P = (2/L) * Y @ Wo^T   (rotated index)
        float pr = 0.f, pi = 0.f;
        #pragma unroll 8
        for (int k = 0; k < 32; ++k) {
            const int jj = (j + k) & 31;
            const float wv = sWo[j*DM + jj];
            pr = fmaf(Yr[(m<<5) + jj], wv, pr);
            pi = fmaf(Yi[(m<<5) + jj], wv, pi);
        }
        Pr[tid] = pr * (2.0f/(float)LSEQ);
        Pi[tid] = pi * (2.0f/(float)LSEQ);
    }
    __syncthreads();

    // ---- inverse 3-mode transform + residual (in place in sx) ----
    {
        const float PrR0 = Pr[0*32 + lane], PiR0 = Pi[0*32 + lane];
        const float PrR1 = Pr[1*32 + lane], PiR1 = Pi[1*32 + lane];
        const float PrR2 = Pr[2*32 + lane], PiR2 = Pi[2*32 + lane];
        const float bod = __ldg(bo + lane);
        #pragma unroll 6
        for (int i = 0; i < 24; ++i) {
            const int t = (i << 2) + w;
            const float2 w1 = tw[t];
            const float2 w2 = tw[LSEQ + t];
            const float2 w3 = tw[2*LSEQ + t];
            float acc = bod;
            acc = fmaf(PrR0, w1.x, acc); acc = fmaf(-PiR0, w1.y, acc);
            acc = fmaf(PrR1, w2.x, acc); acc = fmaf(-PiR1, w2.y, acc);
            acc = fmaf(PrR2, w3.x, acc); acc = fmaf(-PiR2, w3.y, acc);
            sx[t*DM + lane] += acc;
        }
    }
    __syncthreads();

    // ---- sliding-window moving average + residual; warp w owns t in [24w, 24w+24) ----
    {
        const int t0 = w * 24;
        float win = 0.f;
        #pragma unroll
        for (int j = -PAD; j <= PAD; ++j) {
            int tt = t0 + j;
            tt = tt < 0 ? 0 : (tt > LSEQ-1 ? LSEQ-1 : tt);
            win += sx[tt*DM + lane];
        }
        float* og = out + base;
        #pragma unroll 6
        for (int i = 0; i < 24; ++i) {
            const int t = t0 + i;
            og[t*DM + lane] = sx[t*DM + lane] - win * (1.0f/(float)KAVG);
            int thi = t + PAD + 1; thi = thi > LSEQ-1 ? LSEQ-1 : thi;
            int tlo = t - PAD;     tlo = tlo < 0 ? 0 : tlo;
            win += sx[thi*DM + lane] - sx[tlo*DM + lane];
        }
    }
}

extern "C" void kernel_launch(void* const* d_in, const int* in_sizes, int n_in,
                              void* d_out, int out_size) {
    // metadata order: x, Wq, bq, Wk, bk, Wv, bv, Wo, bo, W1, W2
    const float* x  = (const float*)d_in[0];
    const float* Wq = (const float*)d_in[1];
    const float* Wo = (const float*)d_in[7];
    const float* bo = (const float*)d_in[8];
    const float* W1 = (const float*)d_in[9];
    const float* W2 = (const float*)d_in[10];
    float* out = (float*)d_out;

    const int B = in_sizes[0] / (NNODES * LSEQ * DM);
    dim3 grid(NNODES * B);
    feldm_kernel<<<grid, TPB>>>(x, Wq, Wo, bo, W1, W2, out);
}